// round 13
// baseline (speedup 1.0000x reference)
#include <cuda_runtime.h>

// Net_90434831385322: z = LIM_A + span*sigmoid( relu(((x-LIM_A)/span) @ W1 + b1) @ W2 + b2 )
//
// R13 (delta vs R12 best): manual double-buffered prefetch of const-bank
// weights. One jp's weights = 18 URs; unroll-8 hoisting needs ~144 URs > 64
// available, so ptxas serializes LDCU reuse -> ~17% fma-pipe bubbles. Explicit
// jp+1 prefetch bounds UR pressure to 2x18 and hides the ~30cyc LDCU latency
// behind 64 fma-cycles of compute. Rotation is uniform-pipe UMOVs (free).

typedef unsigned long long u64;

__device__ __forceinline__ u64 ffma2(u64 a, u64 b, u64 c) {
    u64 d;
    asm("fma.rn.f32x2 %0, %1, %2, %3;" : "=l"(d) : "l"(a), "l"(b), "l"(c));
    return d;
}
__device__ __forceinline__ u64 pack2(float lo, float hi) {
    u64 d;
    asm("mov.b64 %0, {%1, %2};" : "=l"(d) : "f"(lo), "f"(hi));
    return d;
}
__device__ __forceinline__ void unpack2(u64 v, float& lo, float& hi) {
    asm("mov.b64 {%0, %1}, %2;" : "=f"(lo), "=f"(hi) : "l"(v));
}
__device__ __forceinline__ u64 relu2(u64 h) {
    float a, b;
    unpack2(h, a, b);
    a = fmaxf(a, 0.0f);
    b = fmaxf(b, 0.0f);
    return pack2(a, b);
}
__device__ __forceinline__ float tanh_approx(float v) {
    float r;
    asm("tanh.approx.f32 %0, %1;" : "=f"(r) : "f"(v));
    return r;
}

#define HID 64
#define NJP 32             // hidden-unit pairs
#define NR 4               // rows per thread
#define ROWS_PER_WARP 128  // 32 lanes * 4 rows

struct Fold {
    ulonglong2 A[NJP];
    ulonglong2 B[NJP];
    ulonglong2 C[NJP];
    ulonglong2 D[NJP];
    u64        E[NJP];
    float      bb[4];
};

__device__    Fold gFold;   // staging (written by setup kernel)
__constant__  Fold cFold;   // read by main kernel via const path (LDCU->UR)

__global__ void fold_kernel(const float* __restrict__ W1,   // [4][64]
                            const float* __restrict__ b1,   // [64]
                            const float* __restrict__ W2,   // [64][4]
                            const float* __restrict__ b2)   // [4]
{
    const int jp = threadIdx.x;
    if (jp < NJP) {
        const float lim_a[4]    = {0.001f, 0.02f, 0.05f, 0.001f};
        const float inv_span[4] = {1.0f/0.003f, 1.0f/0.03f, 1.0f/0.15f, 1.0f/0.003f};
        const int j0 = 2 * jp, j1 = 2 * jp + 1;
        float w0[4], w1[4];
        float bf0 = b1[j0], bf1 = b1[j1];
        #pragma unroll
        for (int i = 0; i < 4; i++) {
            w0[i] = W1[i * HID + j0] * inv_span[i];
            w1[i] = W1[i * HID + j1] * inv_span[i];
            bf0 -= lim_a[i] * w0[i];
            bf1 -= lim_a[i] * w1[i];
        }
        gFold.A[jp] = make_ulonglong2(pack2(w0[0], w1[0]), pack2(w0[1], w1[1]));
        gFold.B[jp] = make_ulonglong2(pack2(w0[2], w1[2]), pack2(w0[3], w1[3]));
        gFold.C[jp] = make_ulonglong2(pack2(W2[j0*4+0], W2[j1*4+0]),
                                      pack2(W2[j0*4+1], W2[j1*4+1]));
        gFold.D[jp] = make_ulonglong2(pack2(W2[j0*4+2], W2[j1*4+2]),
                                      pack2(W2[j0*4+3], W2[j1*4+3]));
        gFold.E[jp] = pack2(bf0, bf1);
        if (jp < 4) gFold.bb[jp] = b2[jp];
    }
}

__global__ void __launch_bounds__(128, 7)
mlp_kernel(const float4* __restrict__ x,
           float4* __restrict__ out,
           int rows)
{
    const int t = threadIdx.x;
    const int lane = t & 31;
    const int warp = t >> 5;
    const int warpsPerBlock = blockDim.x >> 5;
    const int base = (blockIdx.x * warpsPerBlock + warp) * ROWS_PER_WARP + lane;

    const bool full = (base + 32 * (NR - 1)) < rows;

    // ---- load NR rows, duplicate each x_i into both lanes ----
    u64 xd[NR][4];
    #pragma unroll
    for (int rr = 0; rr < NR; rr++) {
        int r = base + 32 * rr;
        if (!full) r = r < rows ? r : (rows - 1);
        const float4 a = x[r];
        xd[rr][0] = pack2(a.x, a.x);
        xd[rr][1] = pack2(a.y, a.y);
        xd[rr][2] = pack2(a.z, a.z);
        xd[rr][3] = pack2(a.w, a.w);
    }

    // ---- accumulators: lanes = (partial even j, partial odd j);
    //      b2 bias pre-loaded into the even lane ----
    u64 y[NR][4];
    #pragma unroll
    for (int rr = 0; rr < NR; rr++) {
        #pragma unroll
        for (int k = 0; k < 4; k++) {
            y[rr][k] = pack2(cFold.bb[k], 0.0f);
        }
    }

    // ---- fused layer1 + relu + layer2, double-buffered weight prefetch ----
    ulonglong2 wA = cFold.A[0];
    ulonglong2 wB = cFold.B[0];
    ulonglong2 wC = cFold.C[0];
    ulonglong2 wD = cFold.D[0];
    u64        bE = cFold.E[0];

    #pragma unroll 4
    for (int jp = 0; jp < NJP; jp++) {
        // prefetch next iteration's weights (wraps harmlessly at the end)
        const int nx = (jp + 1) & (NJP - 1);
        const ulonglong2 nA = cFold.A[nx];
        const ulonglong2 nB = cFold.B[nx];
        const ulonglong2 nC = cFold.C[nx];
        const ulonglong2 nD = cFold.D[nx];
        const u64        nE = cFold.E[nx];

        #pragma unroll
        for (int rr = 0; rr < NR; rr++) {
            u64 h = ffma2(xd[rr][0], wA.x, bE);
            h = ffma2(xd[rr][1], wA.y, h);
            h = ffma2(xd[rr][2], wB.x, h);
            h = ffma2(xd[rr][3], wB.y, h);
            h = relu2(h);   // (h_j, h_j+1) for this row
            y[rr][0] = ffma2(h, wC.x, y[rr][0]);
            y[rr][1] = ffma2(h, wC.y, y[rr][1]);
            y[rr][2] = ffma2(h, wD.x, y[rr][2]);
            y[rr][3] = ffma2(h, wD.y, y[rr][3]);
        }

        wA = nA; wB = nB; wC = nC; wD = nD; bE = nE;
    }

    // ---- tanh epilogue + coalesced stores ----
    //  z_k = (lim_a_k + span_k/2) + (span_k/2) * tanh(y_k/2)
    const float c0_k[4] = {0.0025f, 0.035f, 0.125f, 0.0025f};
    const float c1_k[4] = {0.0015f, 0.015f, 0.075f, 0.0015f};

    #pragma unroll
    for (int rr = 0; rr < NR; rr++) {
        float4 o;
        float* p = &o.x;
        #pragma unroll
        for (int k = 0; k < 4; k++) {
            float ye, yo;
            unpack2(y[rr][k], ye, yo);
            const float yk = ye + yo;          // bias already in ye
            const float th = tanh_approx(0.5f * yk);
            p[k] = fmaf(c1_k[k], th, c0_k[k]);
        }
        const int r = base + 32 * rr;
        if (full) {
            out[r] = o;
        } else {
            if (r < rows) out[r] = o;
        }
    }
}

extern "C" void kernel_launch(void* const* d_in, const int* in_sizes, int n_in,
                              void* d_out, int out_size) {
    const float* x  = (const float*)d_in[0];
    const float* W1 = (const float*)d_in[1];
    const float* b1 = (const float*)d_in[2];
    const float* W2 = (const float*)d_in[3];
    const float* b2 = (const float*)d_in[4];
    const int rows = in_sizes[0] / 4;

    // 1) fold weights into staging global
    fold_kernel<<<1, 32>>>(W1, b1, W2, b2);

    // 2) D2D copy into __constant__ (graph-capturable memcpy node)
    void* gptr = nullptr;
    cudaGetSymbolAddress(&gptr, gFold);
    cudaMemcpyToSymbolAsync(cFold, gptr, sizeof(Fold), 0,
                            cudaMemcpyDeviceToDevice);

    // 3) main kernel: flat grid, one 128-row tile per warp, 128-thread CTAs
    const int threads = 128;
    const int rowsPerBlock = (threads / 32) * ROWS_PER_WARP;  // 512
    const int blocks = (rows + rowsPerBlock - 1) / rowsPerBlock;  // 8192
    mlp_kernel<<<blocks, threads>>>((const float4*)x, (float4*)d_out, rows);
}

// round 14
// speedup vs baseline: 1.0494x; 1.0494x over previous
#include <cuda_runtime.h>

// Net_90434831385322: z = LIM_A + span*sigmoid( relu(((x-LIM_A)/span) @ W1 + b1) @ W2 + b2 )
//
// R14 (delta vs R12 best): NR=4 -> 6 rows per thread. Fixed per-body costs
// (prologue LDG wait, 160 LDCU slots, MUFU tail, loop overhead) amortize over
// 6 rows instead of 4; per-row ffma2 work invariant. Occupancy drops to 16
// warps/SM, proven perf-neutral in R4/R5/R12 sweeps.
// R13's UR rotation rejected (alu-pipe flood).

typedef unsigned long long u64;

__device__ __forceinline__ u64 ffma2(u64 a, u64 b, u64 c) {
    u64 d;
    asm("fma.rn.f32x2 %0, %1, %2, %3;" : "=l"(d) : "l"(a), "l"(b), "l"(c));
    return d;
}
__device__ __forceinline__ u64 pack2(float lo, float hi) {
    u64 d;
    asm("mov.b64 %0, {%1, %2};" : "=l"(d) : "f"(lo), "f"(hi));
    return d;
}
__device__ __forceinline__ void unpack2(u64 v, float& lo, float& hi) {
    asm("mov.b64 {%0, %1}, %2;" : "=f"(lo), "=f"(hi) : "l"(v));
}
__device__ __forceinline__ u64 relu2(u64 h) {
    float a, b;
    unpack2(h, a, b);
    a = fmaxf(a, 0.0f);
    b = fmaxf(b, 0.0f);
    return pack2(a, b);
}
__device__ __forceinline__ float tanh_approx(float v) {
    float r;
    asm("tanh.approx.f32 %0, %1;" : "=f"(r) : "f"(v));
    return r;
}

#define HID 64
#define NJP 32             // hidden-unit pairs
#define NR 6               // rows per thread
#define ROWS_PER_WARP 192  // 32 lanes * 6 rows

struct Fold {
    ulonglong2 A[NJP];
    ulonglong2 B[NJP];
    ulonglong2 C[NJP];
    ulonglong2 D[NJP];
    u64        E[NJP];
    float      bb[4];
};

__device__    Fold gFold;   // staging (written by setup kernel)
__constant__  Fold cFold;   // read by main kernel via const path (LDCU->UR)

__global__ void fold_kernel(const float* __restrict__ W1,   // [4][64]
                            const float* __restrict__ b1,   // [64]
                            const float* __restrict__ W2,   // [64][4]
                            const float* __restrict__ b2)   // [4]
{
    const int jp = threadIdx.x;
    if (jp < NJP) {
        const float lim_a[4]    = {0.001f, 0.02f, 0.05f, 0.001f};
        const float inv_span[4] = {1.0f/0.003f, 1.0f/0.03f, 1.0f/0.15f, 1.0f/0.003f};
        const int j0 = 2 * jp, j1 = 2 * jp + 1;
        float w0[4], w1[4];
        float bf0 = b1[j0], bf1 = b1[j1];
        #pragma unroll
        for (int i = 0; i < 4; i++) {
            w0[i] = W1[i * HID + j0] * inv_span[i];
            w1[i] = W1[i * HID + j1] * inv_span[i];
            bf0 -= lim_a[i] * w0[i];
            bf1 -= lim_a[i] * w1[i];
        }
        gFold.A[jp] = make_ulonglong2(pack2(w0[0], w1[0]), pack2(w0[1], w1[1]));
        gFold.B[jp] = make_ulonglong2(pack2(w0[2], w1[2]), pack2(w0[3], w1[3]));
        gFold.C[jp] = make_ulonglong2(pack2(W2[j0*4+0], W2[j1*4+0]),
                                      pack2(W2[j0*4+1], W2[j1*4+1]));
        gFold.D[jp] = make_ulonglong2(pack2(W2[j0*4+2], W2[j1*4+2]),
                                      pack2(W2[j0*4+3], W2[j1*4+3]));
        gFold.E[jp] = pack2(bf0, bf1);
        if (jp < 4) gFold.bb[jp] = b2[jp];
    }
}

__global__ void __launch_bounds__(128, 4)
mlp_kernel(const float4* __restrict__ x,
           float4* __restrict__ out,
           int rows)
{
    const int t = threadIdx.x;
    const int lane = t & 31;
    const int warp = t >> 5;
    const int warpsPerBlock = blockDim.x >> 5;
    const int base = (blockIdx.x * warpsPerBlock + warp) * ROWS_PER_WARP + lane;

    const bool full = (base + 32 * (NR - 1)) < rows;

    // ---- load NR rows, duplicate each x_i into both lanes ----
    u64 xd[NR][4];
    #pragma unroll
    for (int rr = 0; rr < NR; rr++) {
        int r = base + 32 * rr;
        if (!full) r = r < rows ? r : (rows - 1);
        const float4 a = x[r];
        xd[rr][0] = pack2(a.x, a.x);
        xd[rr][1] = pack2(a.y, a.y);
        xd[rr][2] = pack2(a.z, a.z);
        xd[rr][3] = pack2(a.w, a.w);
    }

    // ---- accumulators: lanes = (partial even j, partial odd j);
    //      b2 bias pre-loaded into the even lane ----
    u64 y[NR][4];
    #pragma unroll
    for (int rr = 0; rr < NR; rr++) {
        #pragma unroll
        for (int k = 0; k < 4; k++) {
            y[rr][k] = pack2(cFold.bb[k], 0.0f);
        }
    }

    // ---- fused layer1 + relu + layer2 over 32 hidden-unit pairs ----
    #pragma unroll 8
    for (int jp = 0; jp < NJP; jp++) {
        const ulonglong2 wA = cFold.A[jp];
        const ulonglong2 wB = cFold.B[jp];
        const ulonglong2 wC = cFold.C[jp];
        const ulonglong2 wD = cFold.D[jp];
        const u64 b1d = cFold.E[jp];

        #pragma unroll
        for (int rr = 0; rr < NR; rr++) {
            u64 h = ffma2(xd[rr][0], wA.x, b1d);
            h = ffma2(xd[rr][1], wA.y, h);
            h = ffma2(xd[rr][2], wB.x, h);
            h = ffma2(xd[rr][3], wB.y, h);
            h = relu2(h);   // (h_j, h_j+1) for this row
            y[rr][0] = ffma2(h, wC.x, y[rr][0]);
            y[rr][1] = ffma2(h, wC.y, y[rr][1]);
            y[rr][2] = ffma2(h, wD.x, y[rr][2]);
            y[rr][3] = ffma2(h, wD.y, y[rr][3]);
        }
    }

    // ---- tanh epilogue + coalesced stores ----
    //  z_k = (lim_a_k + span_k/2) + (span_k/2) * tanh(y_k/2)
    const float c0_k[4] = {0.0025f, 0.035f, 0.125f, 0.0025f};
    const float c1_k[4] = {0.0015f, 0.015f, 0.075f, 0.0015f};

    #pragma unroll
    for (int rr = 0; rr < NR; rr++) {
        float4 o;
        float* p = &o.x;
        #pragma unroll
        for (int k = 0; k < 4; k++) {
            float ye, yo;
            unpack2(y[rr][k], ye, yo);
            const float yk = ye + yo;          // bias already in ye
            const float th = tanh_approx(0.5f * yk);
            p[k] = fmaf(c1_k[k], th, c0_k[k]);
        }
        const int r = base + 32 * rr;
        if (full) {
            out[r] = o;
        } else {
            if (r < rows) out[r] = o;
        }
    }
}

extern "C" void kernel_launch(void* const* d_in, const int* in_sizes, int n_in,
                              void* d_out, int out_size) {
    const float* x  = (const float*)d_in[0];
    const float* W1 = (const float*)d_in[1];
    const float* b1 = (const float*)d_in[2];
    const float* W2 = (const float*)d_in[3];
    const float* b2 = (const float*)d_in[4];
    const int rows = in_sizes[0] / 4;

    // 1) fold weights into staging global
    fold_kernel<<<1, 32>>>(W1, b1, W2, b2);

    // 2) D2D copy into __constant__ (graph-capturable memcpy node)
    void* gptr = nullptr;
    cudaGetSymbolAddress(&gptr, gFold);
    cudaMemcpyToSymbolAsync(cFold, gptr, sizeof(Fold), 0,
                            cudaMemcpyDeviceToDevice);

    // 3) main kernel: flat grid, one 192-row tile per warp, 128-thread CTAs
    const int threads = 128;
    const int rowsPerBlock = (threads / 32) * ROWS_PER_WARP;  // 768
    const int blocks = (rows + rowsPerBlock - 1) / rowsPerBlock;  // 5462
    mlp_kernel<<<blocks, threads>>>((const float4*)x, (float4*)d_out, rows);
}